// round 6
// baseline (speedup 1.0000x reference)
#include <cuda_runtime.h>
#include <cstdint>

// DisparityWarping fused, 2-tap gather with merged float2 tap loads:
//   x:[4,16,320,1024] f32, disp:[4,1,320,1024] f32 in [0,64)
//   out: warped [4,16,320,1024] ++ mask [4,1,320,1024] (f32 0/1)
//
// gy(i) == i exactly for i>=80 and within i*2^-23 <= 9.6e-6 otherwise, so the
// bilinear reduces to a horizontal 2-tap lerp on row i (dropped off-row taps
// carry weight <= 1e-5 << 1e-3 gate). Horizontal grid math replicates the
// reference op-for-op so x-floor / boundary decisions match bit-for-bit.
//
// Tap merge: x1 == x0+1, so one aligned LDG.64 at (x0>>1) pays the warp's
// ~3.5-line wavefront cost once; a predicated LDG.32 fixes up v1 only for
// odd-x0 lanes (~50%). The (x1>>1 == x0>>1) select also handles the clamped
// edge case x1c == x0c exactly.

#define H 320
#define W 1024
#define C 16
#define NB 4
#define HW (H * W)
#define CHW (C * HW)

__global__ __launch_bounds__(W, 2)
void disparity_warp2_kernel(const float* __restrict__ x,
                            const float* __restrict__ disp,
                            float* __restrict__ out_img,
                            float* __restrict__ out_mask)
{
    const int row = blockIdx.x;          // n*H + i
    const int n = row / H;
    const int i = row - n * H;
    const int j = threadIdx.x;

    __shared__ int smax[W];
    smax[j] = 0;

    const float d = disp[(size_t)row * W + j];

    int trans = j - (int)d;              // trunc == floor (d >= 0)
    if (trans < 0) trans = 0;

    // ---- grid arithmetic, replicating reference fp32 op order exactly
    const float jm  = (float)j - d;
    const float gxn = __fdiv_rn(2.0f * jm, 1023.0f) - 1.0f;
    const float gx  = ((gxn + 1.0f) * 1023.0f) * 0.5f;
    const float t   = __fdiv_rn(2.0f * (float)i, 319.0f);
    const float gyn = t - 1.0f;
    const float gy  = ((gyn + 1.0f) * 319.0f) * 0.5f;

    const float x0f = floorf(gx);
    const float y0f = floorf(gy);
    const float wx1 = gx - x0f;
    const float wx0 = 1.0f - wx1;
    const float wy1 = gy - y0f;
    const float wy0 = 1.0f - wy1;

    // dominant sample row is always i; its exact weight
    const float wD = (y0f == (float)i) ? wy0 : wy1;

    const float x1f = x0f + 1.0f;
    const float vx0 = (x0f >= 0.0f && x0f <= 1023.0f) ? 1.0f : 0.0f;
    const float vx1 = (x1f >= 0.0f && x1f <= 1023.0f) ? 1.0f : 0.0f;

    int x0c = (int)x0f;     x0c = min(max(x0c, 0), W - 1);
    int x1c = (int)x0f + 1; x1c = min(max(x1c, 0), W - 1);

    const float wA0 = (wx0 * wD) * vx0;
    const float wA1 = (wx1 * wD) * vx1;

    const int  b     = x0c >> 1;          // float2 slot holding v0
    const bool odd0  = (x0c & 1) != 0;
    const bool v1_in = ((x1c >> 1) == b); // v1 inside same float2?
    const bool odd1  = (x1c & 1) != 0;

    const float* p  = x       + (size_t)n * CHW + (size_t)i * W;
    float*       ob = out_img + (size_t)n * CHW + (size_t)i * W + j;

    __syncthreads();                      // smax init complete

    #pragma unroll 4
    for (int c = 0; c < C; ++c) {
        const float*  pc  = p + (size_t)c * HW;
        const float2  f2  = __ldg((const float2*)pc + b);
        const float   v0  = odd0 ? f2.y : f2.x;
        float         v1;
        if (v1_in) v1 = odd1 ? f2.y : f2.x;
        else       v1 = __ldg(pc + x1c);
        ob[(size_t)c * HW] = v0 * wA0 + v1 * wA1;
    }

    // occlusion scatter after gather issue (ATOMS hides under LDG latency)
    atomicMax(&smax[trans], j);

    __syncthreads();                      // all atomicMax done
    const int back = smax[trans];
    const int ad = back - j;
    const bool occ = (ad <= 1) && (ad >= -1);
    const bool inb = fabsf(gxn) <= 1.0f;  // |gy_norm|<=1 always true
    out_mask[(size_t)row * W + j] = (occ && inb) ? 1.0f : 0.0f;
}

extern "C" void kernel_launch(void* const* d_in, const int* in_sizes, int n_in,
                              void* d_out, int out_size)
{
    const float* x    = (const float*)d_in[0];
    const float* disp = (const float*)d_in[1];
    float* out_img  = (float*)d_out;
    float* out_mask = (float*)d_out + (size_t)NB * CHW;

    disparity_warp2_kernel<<<NB * H, W>>>(x, disp, out_img, out_mask);
}